// round 6
// baseline (speedup 1.0000x reference)
#include <cuda_runtime.h>

#define IMGSZ 64
#define DSTEPS 64
#define NB 4
#define DSH 61
#define H1 128
#define NPIX (IMGSZ * IMGSZ)

// scratch (no allocations allowed)
__device__ float g_hb[NB][H1];     // per-batch hidden bias (b1 + B-part + z_shape part)
__device__ float g_cst[NB][12];    // M[9] (partial), s_inv, bb_depth, invDen

// ---------------------------------------------------------------------------
// Precompute per-batch constants.
// grid = NB blocks, 128 threads (one per hidden unit)
// ---------------------------------------------------------------------------
__global__ void precomp_kernel(const float* __restrict__ z_shape,
                               const float* __restrict__ z_extr,
                               const float* __restrict__ W1,
                               const float* __restrict__ b1) {
    int b = blockIdx.x;
    int j = threadIdx.x;  // 0..127

    float scale = z_extr[b * 5 + 0];
    float tox   = z_extr[b * 5 + 1];
    float toy   = z_extr[b * 5 + 2];
    float toz   = z_extr[b * 5 + 3];
    float alpha = z_extr[b * 5 + 4];

    float s_obj = 1.0f / scale;          // reference: s_obj = 1/z_extr[:,0]
    float s_inv = 1.0f / s_obj;          // reference: s_inv = 1/s_obj
    float ang = 3.14159265358979323846f * alpha;
    float ca = cosf(ang), sa = sinf(ang);

    // R_obj = Z-rotation; K_inv = [[1/f,0,-c/f],[0,1/f,-c/f],[0,0,1]], f=70, c=31.5
    const float f = 70.0f;
    const float cc = 31.5f;
    float invf = 1.0f / f;
    float Ki02 = -cc * invf;

    // M = s_obj * R_obj @ K_inv
    float M00 = s_obj * ( ca * invf);
    float M01 = s_obj * (-sa * invf);
    float M02 = s_obj * ( ca * Ki02 + (-sa) * Ki02);
    float M10 = s_obj * ( sa * invf);
    float M11 = s_obj * ( ca * invf);
    float M12 = s_obj * ( sa * Ki02 + ( ca) * Ki02);
    float M22 = s_obj;

    // B = s_obj * R_obj @ (-t - t_obj), t = (0,0,2.5)
    float wx = -tox, wy = -toy, wz = -2.5f - toz;
    float Bx = s_obj * (ca * wx + (-sa) * wy);
    float By = s_obj * (sa * wx + ( ca) * wy);
    float Bz = s_obj * wz;

    // bb_depth: mean camera-z of 9 bbox points (rotation about z keeps z-comp)
    const float cz[9] = {1.f,-1.f,1.f,-1.f,1.f,-1.f,1.f,-1.f,0.f};
    float acc = 0.f;
    #pragma unroll
    for (int a = 0; a < 9; a++) acc += s_inv * cz[a] + toz + 2.5f;
    float bb = acc / 9.0f;

    // hidden bias: b1 + B·W1[0:3] + z_shape·W1[3:]
    float h = b1[j];
    h += Bx * W1[0 * H1 + j];
    h += By * W1[1 * H1 + j];
    h += Bz * W1[2 * H1 + j];
    #pragma unroll 4
    for (int ff = 0; ff < DSH; ff++)
        h += z_shape[b * DSH + ff] * W1[(3 + ff) * H1 + j];
    g_hb[b][j] = h;

    if (j == 0) {
        g_cst[b][0] = M00; g_cst[b][1] = M01; g_cst[b][2] = M02;
        g_cst[b][3] = M10; g_cst[b][4] = M11; g_cst[b][5] = M12;
        g_cst[b][6] = 0.f; g_cst[b][7] = 0.f; g_cst[b][8] = M22;
        g_cst[b][9] = s_inv; g_cst[b][10] = bb;
        g_cst[b][11] = 1.0f / (s_inv * (2.0f / 63.0f));   // invDen (d per unit Z)
    }
}

// ---------------------------------------------------------------------------
// Render via piecewise-linear evaluation.
// acc(d) = SA(d) + Z_d * SB(d), SA/SB = prefix sums of per-unit (w2*hb, w2*g)
// over the d-interval where the unit's relu is active.
// 1 warp per ray; lane l owns hidden units 4l..4l+3 and depth bins 2l, 2l+1.
// ---------------------------------------------------------------------------
__global__ __launch_bounds__(256) void render_kernel(
    const float* __restrict__ W1, const float* __restrict__ W2,
    const float* __restrict__ b2, float* __restrict__ out) {

    __shared__ __align__(8) float s_dA[8][66];  // difference bins, per warp
    __shared__ __align__(8) float s_dB[8][66];

    int tid  = threadIdx.x;
    int warp = tid >> 5;
    int lane = tid & 31;
    int ray  = blockIdx.x * 8 + warp;
    int b    = ray >> 12;                // 4096 rays per batch
    int p    = ray & (NPIX - 1);
    float x  = (float)(p & 63);          // meshgrid 'xy': x fastest
    float y  = (float)(p >> 6);

    const float* cst = g_cst[b];
    float Ax = cst[0] * x + cst[1] * y + cst[2];
    float Ay = cst[3] * x + cst[4] * y + cst[5];
    float Az = cst[8];
    float s_inv = cst[9], bb = cst[10], invDen = cst[11];
    float b2v = b2[0];
    float Zbase = bb - s_inv;            // Z at d=0

    float* dA = s_dA[warp];
    float* dB = s_dB[warp];
    // zero bins (fold b2 into bin 0 of dA so SA includes it for all d)
    ((float2*)dA)[lane] = make_float2(lane == 0 ? b2v : 0.f, 0.f);
    ((float2*)dB)[lane] = make_float2(0.f, 0.f);
    if (lane == 0) {
        ((float2*)dA)[32] = make_float2(0.f, 0.f);
        ((float2*)dB)[32] = make_float2(0.f, 0.f);
    }

    int j4 = lane * 4;
    float4 wxv = *(const float4*)(W1 + j4);
    float4 wyv = *(const float4*)(W1 + H1 + j4);
    float4 wzv = *(const float4*)(W1 + 2 * H1 + j4);
    float4 hb4 = *(const float4*)(&g_hb[b][j4]);
    float4 w24 = *(const float4*)(W2 + j4);

    float gv[4], hv[4], wv[4];
    gv[0] = fmaf(Ax, wxv.x, fmaf(Ay, wyv.x, Az * wzv.x));
    gv[1] = fmaf(Ax, wxv.y, fmaf(Ay, wyv.y, Az * wzv.y));
    gv[2] = fmaf(Ax, wxv.z, fmaf(Ay, wyv.z, Az * wzv.z));
    gv[3] = fmaf(Ax, wxv.w, fmaf(Ay, wyv.w, Az * wzv.w));
    hv[0] = hb4.x; hv[1] = hb4.y; hv[2] = hb4.z; hv[3] = hb4.w;
    wv[0] = w24.x; wv[1] = w24.y; wv[2] = w24.z; wv[3] = w24.w;

    __syncwarp();   // bin zeroing visible before atomics

    #pragma unroll
    for (int k = 0; k < 4; k++) {
        float gk = gv[k], hk = hv[k], wk = wv[k];
        float a  = wk * hk;
        float bc = wk * gk;
        if (gk > 0.f) {
            // active for d-index > u
            float u = (__fdividef(-hk, gk) - Zbase) * invDen;
            u = fminf(fmaxf(u, -1.f), 64.f);
            int dlo = (int)floorf(u) + 1;      // in [0,65]
            atomicAdd(dA + dlo, a);
            atomicAdd(dB + dlo, bc);
        } else if (gk < 0.f) {
            // active for d-index < u
            float u = (__fdividef(-hk, gk) - Zbase) * invDen;
            u = fminf(fmaxf(u, 0.f), 64.f);
            int cut = (int)ceilf(u);           // in [0,64]
            atomicAdd(dA, a);
            atomicAdd(dB, bc);
            atomicAdd(dA + cut, -a);
            atomicAdd(dB + cut, -bc);
        } else if (hk > 0.f) {
            atomicAdd(dA, a);                  // bc = wk*0 = 0
        }
    }
    __syncwarp();

    // inclusive prefix scan over 64 bins (2 bins / lane)
    float2 vA = ((const float2*)dA)[lane];
    float2 vB = ((const float2*)dB)[lane];
    float lsA = vA.x + vA.y, lsB = vB.x + vB.y;
    float sA = lsA, sB = lsB;
    #pragma unroll
    for (int o = 1; o < 32; o <<= 1) {
        float tA = __shfl_up_sync(0xffffffffu, sA, o);
        float tB = __shfl_up_sync(0xffffffffu, sB, o);
        if (lane >= o) { sA += tA; sB += tB; }
    }
    float eA = sA - lsA, eB = sB - lsB;        // exclusive
    float SA0 = eA + vA.x, SB0 = eB + vB.x;    // inclusive at bin 2l
    float SA1 = sA,        SB1 = sB;           // inclusive at bin 2l+1

    const float zstep = 2.0f / 63.0f;
    int d0 = 2 * lane;
    float Z0 = fmaf(-1.0f + (float)(d0    ) * zstep, s_inv, bb);
    float Z1 = fmaf(-1.0f + (float)(d0 + 1) * zstep, s_inv, bb);
    float Z2 = fmaf(-1.0f + (float)(d0 + 2) * zstep, s_inv, bb);

    float acc0 = fmaf(Z0, SB0, SA0);           // includes b2 via bin 0
    float acc1 = fmaf(Z1, SB1, SA1);
    float sdf0, sdf1;
    asm("tanh.approx.f32 %0, %1;" : "=f"(sdf0) : "f"(acc0));
    asm("tanh.approx.f32 %0, %1;" : "=f"(sdf1) : "f"(acc1));

    // neighbor values (depth 2l+2 lives in lane l+1)
    float accn = __shfl_down_sync(0xffffffffu, acc0, 1);
    float nxt  = __shfl_down_sync(0xffffffffu, sdf0, 1);

    bool cra = (acc0 > 0.f) && (acc1 <= 0.f);                // pair (2l, 2l+1)
    bool crb = (lane < 31) && (acc1 > 0.f) && (accn <= 0.f); // pair (2l+1, 2l+2)

    float s1 = (cra ? sdf0 : 0.f) + (crb ? sdf1 : 0.f);
    float s2 = (cra ? sdf1 : 0.f) + (crb ? nxt  : 0.f);
    float d1 = fminf(cra ? Z0 : 100.f, crb ? Z1 : 100.f);
    float d2 = fminf(cra ? Z1 : 100.f, crb ? Z2 : 100.f);

    #pragma unroll
    for (int o = 16; o; o >>= 1) {
        s1 += __shfl_xor_sync(0xffffffffu, s1, o);
        s2 += __shfl_xor_sync(0xffffffffu, s2, o);
        d1  = fminf(d1, __shfl_xor_sync(0xffffffffu, d1, o));
        d2  = fminf(d2, __shfl_xor_sync(0xffffffffu, d2, o));
    }

    if (lane == 0) {
        float occ = (d1 < 99.f) ? 1.f : 0.f;
        float depth = occ * (d1 - s1 / (s2 - s1 - 1e-6f) * (d2 - d1));
        out[ray] = depth;                 // depth_pred (BS,64,64,1)
        out[NB * NPIX + ray] = occ;       // occ        (BS,64,64,1)
    }
}

extern "C" void kernel_launch(void* const* d_in, const int* in_sizes, int n_in,
                              void* d_out, int out_size) {
    const float* z_shape = (const float*)d_in[0];  // (4,61)
    const float* z_extr  = (const float*)d_in[1];  // (4,5)
    const float* W1      = (const float*)d_in[2];  // (64,128)
    const float* b1      = (const float*)d_in[3];  // (128,)
    const float* W2      = (const float*)d_in[4];  // (128,1)
    const float* b2      = (const float*)d_in[5];  // (1,)
    float* out = (float*)d_out;

    precomp_kernel<<<NB, H1>>>(z_shape, z_extr, W1, b1);
    render_kernel<<<(NB * NPIX) / 8, 256>>>(W1, W2, b2, out);
}

// round 7
// speedup vs baseline: 3.0447x; 3.0447x over previous
#include <cuda_runtime.h>

#define IMGSZ 64
#define DSTEPS 64
#define NB 4
#define DSH 61
#define H1 128
#define NPIX (IMGSZ * IMGSZ)

// scratch (no allocations allowed)
__device__ float g_hb[NB][H1];     // (w2/2)*hidden-bias  per batch
__device__ float g_w1s[3][H1];     // (w2/2)-scaled W1 rows (batch-independent)
__device__ float g_sg[H1];         // sign(w2) as +-1.0f    (batch-independent)
__device__ float g_cst[NB][16];    // M(6), M22, s_inv, bb, C_A, v[3]

// ---------------------------------------------------------------------------
// Precompute per-batch constants + scaled/folded MLP arrays.
// grid = NB blocks, 128 threads (one per hidden unit)
// ---------------------------------------------------------------------------
__global__ void precomp_kernel(const float* __restrict__ z_shape,
                               const float* __restrict__ z_extr,
                               const float* __restrict__ W1,
                               const float* __restrict__ b1,
                               const float* __restrict__ W2,
                               const float* __restrict__ b2) {
    int b = blockIdx.x;
    int j = threadIdx.x;  // 0..127

    float scale = z_extr[b * 5 + 0];
    float tox   = z_extr[b * 5 + 1];
    float toy   = z_extr[b * 5 + 2];
    float toz   = z_extr[b * 5 + 3];
    float alpha = z_extr[b * 5 + 4];

    float s_obj = 1.0f / scale;          // reference: s_obj = 1/z_extr[:,0]
    float s_inv = 1.0f / s_obj;          // reference: s_inv = 1/s_obj
    float ang = 3.14159265358979323846f * alpha;
    float ca = cosf(ang), sa = sinf(ang);

    // R_obj = Z-rotation; K_inv = [[1/f,0,-c/f],[0,1/f,-c/f],[0,0,1]], f=70, c=31.5
    const float f = 70.0f;
    const float cc = 31.5f;
    float invf = 1.0f / f;
    float Ki02 = -cc * invf;

    // M = s_obj * R_obj @ K_inv
    float M00 = s_obj * ( ca * invf);
    float M01 = s_obj * (-sa * invf);
    float M02 = s_obj * ( ca * Ki02 + (-sa) * Ki02);
    float M10 = s_obj * ( sa * invf);
    float M11 = s_obj * ( ca * invf);
    float M12 = s_obj * ( sa * Ki02 + ( ca) * Ki02);
    float M22 = s_obj;

    // B = s_obj * R_obj @ (-t - t_obj), t = (0,0,2.5)
    float wx = -tox, wy = -toy, wz = -2.5f - toz;
    float Bx = s_obj * (ca * wx + (-sa) * wy);
    float By = s_obj * (sa * wx + ( ca) * wy);
    float Bz = s_obj * wz;

    // bb_depth: mean camera-z of 9 bbox points (rotation about z keeps z-comp)
    const float cz[9] = {1.f,-1.f,1.f,-1.f,1.f,-1.f,1.f,-1.f,0.f};
    float acc = 0.f;
    #pragma unroll
    for (int a = 0; a < 9; a++) acc += s_inv * cz[a] + toz + 2.5f;
    float bb = acc / 9.0f;

    // hidden bias: b1 + B·W1[0:3] + z_shape·W1[3:]
    float w1x = W1[0 * H1 + j];
    float w1y = W1[1 * H1 + j];
    float w1z = W1[2 * H1 + j];
    float h = b1[j];
    h += Bx * w1x;
    h += By * w1y;
    h += Bz * w1z;
    #pragma unroll 4
    for (int ff = 0; ff < DSH; ff++)
        h += z_shape[b * DSH + ff] * W1[(3 + ff) * H1 + j];

    // fold w2/2 into everything (relu(x) = (x+|x|)/2 trick)
    float w2  = W2[j];
    float m   = 0.5f * w2;
    float hbp = m * h;
    float wsx = m * w1x, wsy = m * w1y, wsz = m * w1z;

    g_hb[b][j] = hbp;
    if (b == 0) {
        g_w1s[0][j] = wsx;
        g_w1s[1][j] = wsy;
        g_w1s[2][j] = wsz;
        g_sg[j] = (w2 >= 0.f) ? 1.0f : -1.0f;
    }

    // block reduction for affine part: C_A = sum(hbp)+b2, v = row sums of W1s
    __shared__ float4 red[H1];
    red[j] = make_float4(hbp, wsx, wsy, wsz);
    __syncthreads();
    #pragma unroll
    for (int off = 64; off; off >>= 1) {
        if (j < off) {
            float4 a2 = red[j], c2 = red[j + off];
            red[j] = make_float4(a2.x + c2.x, a2.y + c2.y, a2.z + c2.z, a2.w + c2.w);
        }
        __syncthreads();
    }

    if (j == 0) {
        float* cst = g_cst[b];
        cst[0] = M00; cst[1] = M01; cst[2] = M02;
        cst[3] = M10; cst[4] = M11; cst[5] = M12;
        cst[6] = 0.f; cst[7] = 0.f; cst[8] = M22;
        cst[9] = s_inv; cst[10] = bb;
        cst[11] = red[0].x + b2[0];     // C_A (b2 folded in)
        cst[12] = red[0].y;             // v.x
        cst[13] = red[0].z;             // v.y
        cst[14] = red[0].w;             // v.z
        cst[15] = 0.f;
    }
}

// ---------------------------------------------------------------------------
// Render: 1 warp per ray; lane l owns depths 2l, 2l+1.
// acc(Z) = C_A + Z*(A.v) + sum_j sign(w2_j)*|hb'_j + Z*g'_j|
// Per (unit, depth): exactly 2 FFMA (|src| modifier folds the abs for free).
// ---------------------------------------------------------------------------
__global__ __launch_bounds__(256) void render_kernel(float* __restrict__ out) {

    __shared__ __align__(16) float s_g[8][H1];   // per-warp per-ray g'
    __shared__ __align__(16) float s_hb[H1];     // per-batch hb'
    __shared__ __align__(16) float s_s[H1];      // signs

    int tid  = threadIdx.x;
    int warp = tid >> 5;
    int lane = tid & 31;
    int ray  = blockIdx.x * 8 + warp;
    int b    = ray >> 12;                // 4096 rays per batch
    int p    = ray & (NPIX - 1);
    float x  = (float)(p & 63);          // meshgrid 'xy': x fastest
    float y  = (float)(p >> 6);

    if (tid < H1) s_hb[tid] = g_hb[b][tid];
    else          s_s[tid - H1] = g_sg[tid - H1];

    const float* cst = g_cst[b];
    float Ax = fmaf(cst[0], x, fmaf(cst[1], y, cst[2]));
    float Ay = fmaf(cst[3], x, fmaf(cst[4], y, cst[5]));
    float Az = cst[8];
    float s_inv = cst[9], bb = cst[10];
    float CA = cst[11];
    float vA = fmaf(Ax, cst[12], fmaf(Ay, cst[13], Az * cst[14]));

    // per-ray gradient g'_j for this lane's 4 units -> shared
    int j4 = lane * 4;
    float4 wxv = *(const float4*)(g_w1s[0] + j4);
    float4 wyv = *(const float4*)(g_w1s[1] + j4);
    float4 wzv = *(const float4*)(g_w1s[2] + j4);
    float4 gq;
    gq.x = fmaf(Ax, wxv.x, fmaf(Ay, wyv.x, Az * wzv.x));
    gq.y = fmaf(Ax, wxv.y, fmaf(Ay, wyv.y, Az * wzv.y));
    gq.z = fmaf(Ax, wxv.z, fmaf(Ay, wyv.z, Az * wzv.z));
    gq.w = fmaf(Ax, wxv.w, fmaf(Ay, wyv.w, Az * wzv.w));
    *(float4*)&s_g[warp][j4] = gq;
    __syncthreads();

    const float zstep = 2.0f / 63.0f;
    int d0 = 2 * lane;
    float Z0 = fmaf(-1.0f + (float)(d0    ) * zstep, s_inv, bb);
    float Z1 = fmaf(-1.0f + (float)(d0 + 1) * zstep, s_inv, bb);
    float Z2 = fmaf(-1.0f + (float)(d0 + 2) * zstep, s_inv, bb);

    float acc0 = fmaf(Z0, vA, CA);
    float acc1 = fmaf(Z1, vA, CA);

    #pragma unroll
    for (int j = 0; j < H1; j += 4) {
        float4 g  = *(const float4*)&s_g[warp][j];
        float4 h  = *(const float4*)&s_hb[j];
        float4 sg = *(const float4*)&s_s[j];
        float q;
        q = fmaf(Z0, g.x, h.x); acc0 = fmaf(sg.x, fabsf(q), acc0);
        q = fmaf(Z1, g.x, h.x); acc1 = fmaf(sg.x, fabsf(q), acc1);
        q = fmaf(Z0, g.y, h.y); acc0 = fmaf(sg.y, fabsf(q), acc0);
        q = fmaf(Z1, g.y, h.y); acc1 = fmaf(sg.y, fabsf(q), acc1);
        q = fmaf(Z0, g.z, h.z); acc0 = fmaf(sg.z, fabsf(q), acc0);
        q = fmaf(Z1, g.z, h.z); acc1 = fmaf(sg.z, fabsf(q), acc1);
        q = fmaf(Z0, g.w, h.w); acc0 = fmaf(sg.w, fabsf(q), acc0);
        q = fmaf(Z1, g.w, h.w); acc1 = fmaf(sg.w, fabsf(q), acc1);
    }

    float sdf0, sdf1;
    asm("tanh.approx.f32 %0, %1;" : "=f"(sdf0) : "f"(acc0));
    asm("tanh.approx.f32 %0, %1;" : "=f"(sdf1) : "f"(acc1));

    // neighbor values (depth 2l+2 lives in lane l+1)
    float accn = __shfl_down_sync(0xffffffffu, acc0, 1);
    float nxt  = __shfl_down_sync(0xffffffffu, sdf0, 1);

    bool cra = (acc0 > 0.f) && (acc1 <= 0.f);                // pair (2l, 2l+1)
    bool crb = (lane < 31) && (acc1 > 0.f) && (accn <= 0.f); // pair (2l+1, 2l+2)

    float s1 = (cra ? sdf0 : 0.f) + (crb ? sdf1 : 0.f);
    float s2 = (cra ? sdf1 : 0.f) + (crb ? nxt  : 0.f);
    float d1 = fminf(cra ? Z0 : 100.f, crb ? Z1 : 100.f);
    float d2 = fminf(cra ? Z1 : 100.f, crb ? Z2 : 100.f);

    #pragma unroll
    for (int o = 16; o; o >>= 1) {
        s1 += __shfl_xor_sync(0xffffffffu, s1, o);
        s2 += __shfl_xor_sync(0xffffffffu, s2, o);
        d1  = fminf(d1, __shfl_xor_sync(0xffffffffu, d1, o));
        d2  = fminf(d2, __shfl_xor_sync(0xffffffffu, d2, o));
    }

    if (lane == 0) {
        float occ = (d1 < 99.f) ? 1.f : 0.f;
        float depth = occ * (d1 - s1 / (s2 - s1 - 1e-6f) * (d2 - d1));
        out[ray] = depth;                 // depth_pred (BS,64,64,1)
        out[NB * NPIX + ray] = occ;       // occ        (BS,64,64,1)
    }
}

extern "C" void kernel_launch(void* const* d_in, const int* in_sizes, int n_in,
                              void* d_out, int out_size) {
    const float* z_shape = (const float*)d_in[0];  // (4,61)
    const float* z_extr  = (const float*)d_in[1];  // (4,5)
    const float* W1      = (const float*)d_in[2];  // (64,128)
    const float* b1      = (const float*)d_in[3];  // (128,)
    const float* W2      = (const float*)d_in[4];  // (128,1)
    const float* b2      = (const float*)d_in[5];  // (1,)
    float* out = (float*)d_out;

    precomp_kernel<<<NB, H1>>>(z_shape, z_extr, W1, b1, W2, b2);
    render_kernel<<<(NB * NPIX) / 8, 256>>>(out);
}